// round 6
// baseline (speedup 1.0000x reference)
#include <cuda_runtime.h>
#include <cstdint>
#include <cstddef>

#define B_ 1024
#define G_ 256
#define K_ 256
#define E_ 64
#define BETA_F 0.05f

// ---------------- packed fp32x2 helpers (Blackwell FFMA2 path) -----------------
__device__ __forceinline__ void ffma2(unsigned long long &d,
                                      unsigned long long a, unsigned long long b) {
    asm("fma.rn.f32x2 %0, %1, %2, %0;" : "+l"(d) : "l"(a), "l"(b));
}
__device__ __forceinline__ unsigned long long pk2(float lo, float hi) {
    unsigned long long r; asm("mov.b64 %0, {%1, %2};" : "=l"(r) : "f"(lo), "f"(hi));
    return r;
}
__device__ __forceinline__ float2 upk(unsigned long long v) {
    float2 f; asm("mov.b64 {%0, %1}, %2;" : "=f"(f.x), "=f"(f.y) : "l"(v));
    return f;
}

// ---------------- scratch (__device__ globals: no runtime allocation) ----------
__device__ float gM [K_*E_*E_];   // 4 MB : M_k = W_k^T W_k
__device__ float gS6[K_*E_*E_];   // 4 MB : sum_{j=0..5} A^j
__device__ float gR [K_*E_*E_];   // 4 MB : 2b*S5 - b^2*S5*M*S5
__device__ float gV [K_*E_];      // 64KB : v_k = mu_k W_k
__device__ float gMunorm[K_];
__device__ float gScore[B_*K_];   // 1 MB
__device__ int   gKmax[B_];

// ---------------- K1: per-k  M, v, ||mu_k||^2 ----------------------------------
// thread t owns M[e][f0..f0+15], e = t>>2, f0 = (t&3)*16  -> f32x2-packable
__global__ __launch_bounds__(256) void k1_prep(const float* __restrict__ mu,
                                               const float* __restrict__ w)
{
    int k = blockIdx.x;
    int t = threadIdx.x;
    const int e  = t >> 2;
    const int f0 = (t & 3) << 4;
    __shared__ float Ws[64*64];   // [g][e] chunk of W_k
    __shared__ float mus[64];
    __shared__ float red[64];
    unsigned long long acc2[8];
#pragma unroll
    for (int i = 0; i < 8; i++) acc2[i] = 0ULL;
    float vacc = 0.f, mn = 0.f;
    const float* wk = w + (size_t)k * G_ * E_;
    for (int gc = 0; gc < G_; gc += 64) {
        const float* src = wk + (size_t)gc * E_;   // contiguous 4096 floats
        for (int idx = t; idx < 4096; idx += 256) Ws[idx] = src[idx];
        if (t < 64) mus[t] = mu[(size_t)(gc + t) * K_ + k];
        __syncthreads();
#pragma unroll 8
        for (int g = 0; g < 64; g++) {
            float be = Ws[g*64 + e];
            unsigned long long b2 = pk2(be, be);
            const ulonglong2* row = (const ulonglong2*)&Ws[g*64 + f0];
            ulonglong2 r0 = row[0], r1 = row[1], r2 = row[2], r3 = row[3];
            ffma2(acc2[0], b2, r0.x); ffma2(acc2[1], b2, r0.y);
            ffma2(acc2[2], b2, r1.x); ffma2(acc2[3], b2, r1.y);
            ffma2(acc2[4], b2, r2.x); ffma2(acc2[5], b2, r2.y);
            ffma2(acc2[6], b2, r3.x); ffma2(acc2[7], b2, r3.y);
        }
        if (t < 64) {
            float va = 0.f;
#pragma unroll 16
            for (int g = 0; g < 64; g++) va += mus[g] * Ws[g*64 + t];
            vacc += va;
            mn += mus[t] * mus[t];
        }
        __syncthreads();
    }
    float* Mk = gM + (size_t)k * 4096 + e*64 + f0;
#pragma unroll
    for (int p = 0; p < 8; p++) {
        float2 v = upk(acc2[p]);
        *(float2*)&Mk[p*2] = v;
    }
    if (t < 64) { gV[k*E_ + t] = vacc; red[t] = mn; }
    __syncthreads();
    if (t == 0) { float s = 0.f; for (int i = 0; i < 64; i++) s += red[i]; gMunorm[k] = s; }
}

// ---------------- K2: per-k  S6 and R ------------------------------------------
// S_{t+1} = I + A*S_t, A = (1-b)I - b*M.  S_1 = I; after 4 iters Ss = S5.
// S6 = I + (1-b)S5 - b*(M*S5).  R = 2b*S5 - b^2*(M*S5)*S5   (M,S commute, all sym.)
// same f32x2-friendly ownership as k1: thread owns out[e][f0..f0+15].
__global__ __launch_bounds__(256) void k2_poly()
{
    int k = blockIdx.x;
    int t = threadIdx.x;
    const int e  = t >> 2;
    const int f0 = (t & 3) << 4;
    __shared__ float Ms[64*64];
    __shared__ float Ss[64*64];
    const float* Mk = gM + (size_t)k * 4096;
    for (int idx = t; idx < 4096; idx += 256) {
        Ms[idx] = Mk[idx];
        Ss[idx] = ((idx >> 6) == (idx & 63)) ? 1.f : 0.f;
    }
    __syncthreads();

    for (int it = 0; it < 4; it++) {
        unsigned long long a2[8];
#pragma unroll
        for (int p = 0; p < 8; p++) a2[p] = 0ULL;
#pragma unroll 8
        for (int g = 0; g < 64; g++) {
            float me = Ms[e*64 + g];
            unsigned long long b2 = pk2(me, me);
            const ulonglong2* row = (const ulonglong2*)&Ss[g*64 + f0];
            ulonglong2 r0 = row[0], r1 = row[1], r2 = row[2], r3 = row[3];
            ffma2(a2[0], b2, r0.x); ffma2(a2[1], b2, r0.y);
            ffma2(a2[2], b2, r1.x); ffma2(a2[3], b2, r1.y);
            ffma2(a2[4], b2, r2.x); ffma2(a2[5], b2, r2.y);
            ffma2(a2[6], b2, r3.x); ffma2(a2[7], b2, r3.y);
        }
        float nv[16];
#pragma unroll
        for (int p = 0; p < 8; p++) {
            float2 a = upk(a2[p]);
            int f = f0 + p*2;
            float o0 = Ss[e*64 + f], o1 = Ss[e*64 + f + 1];
            nv[p*2]   = (1.f - BETA_F)*o0 - BETA_F*a.x + ((e == f  ) ? 1.f : 0.f);
            nv[p*2+1] = (1.f - BETA_F)*o1 - BETA_F*a.y + ((e == f+1) ? 1.f : 0.f);
        }
        __syncthreads();
#pragma unroll
        for (int p = 0; p < 16; p++) Ss[e*64 + f0 + p] = nv[p];
        __syncthreads();
    }

    // Ss = S5. ms5 = M*S5; S6 -> gmem; Ms := ms5.
    {
        unsigned long long a2[8];
#pragma unroll
        for (int p = 0; p < 8; p++) a2[p] = 0ULL;
#pragma unroll 8
        for (int g = 0; g < 64; g++) {
            float me = Ms[e*64 + g];
            unsigned long long b2 = pk2(me, me);
            const ulonglong2* row = (const ulonglong2*)&Ss[g*64 + f0];
            ulonglong2 r0 = row[0], r1 = row[1], r2 = row[2], r3 = row[3];
            ffma2(a2[0], b2, r0.x); ffma2(a2[1], b2, r0.y);
            ffma2(a2[2], b2, r1.x); ffma2(a2[3], b2, r1.y);
            ffma2(a2[4], b2, r2.x); ffma2(a2[5], b2, r2.y);
            ffma2(a2[6], b2, r3.x); ffma2(a2[7], b2, r3.y);
        }
        float ms5v[16];
        float* S6o = gS6 + (size_t)k*4096 + e*64 + f0;
#pragma unroll
        for (int p = 0; p < 8; p++) {
            float2 a = upk(a2[p]);
            int f = f0 + p*2;
            ms5v[p*2] = a.x; ms5v[p*2+1] = a.y;
            float s0 = (1.f - BETA_F)*Ss[e*64 + f]     - BETA_F*a.x + ((e == f  ) ? 1.f : 0.f);
            float s1 = (1.f - BETA_F)*Ss[e*64 + f + 1] - BETA_F*a.y + ((e == f+1) ? 1.f : 0.f);
            *(float2*)&S6o[p*2] = make_float2(s0, s1);
        }
        __syncthreads();
#pragma unroll
        for (int p = 0; p < 16; p++) Ms[e*64 + f0 + p] = ms5v[p];
        __syncthreads();
    }

    // Q = (M*S5)*S5 ;  R = 2b*S5 - b^2*Q
    {
        unsigned long long a2[8];
#pragma unroll
        for (int p = 0; p < 8; p++) a2[p] = 0ULL;
#pragma unroll 8
        for (int g = 0; g < 64; g++) {
            float me = Ms[e*64 + g];
            unsigned long long b2 = pk2(me, me);
            const ulonglong2* row = (const ulonglong2*)&Ss[g*64 + f0];
            ulonglong2 r0 = row[0], r1 = row[1], r2 = row[2], r3 = row[3];
            ffma2(a2[0], b2, r0.x); ffma2(a2[1], b2, r0.y);
            ffma2(a2[2], b2, r1.x); ffma2(a2[3], b2, r1.y);
            ffma2(a2[4], b2, r2.x); ffma2(a2[5], b2, r2.y);
            ffma2(a2[6], b2, r3.x); ffma2(a2[7], b2, r3.y);
        }
        float* Ro = gR + (size_t)k*4096 + e*64 + f0;
#pragma unroll
        for (int p = 0; p < 8; p++) {
            float2 q = upk(a2[p]);
            int f = f0 + p*2;
            float r0v = 2.f*BETA_F*Ss[e*64 + f]     - BETA_F*BETA_F*q.x;
            float r1v = 2.f*BETA_F*Ss[e*64 + f + 1] - BETA_F*BETA_F*q.y;
            *(float2*)&Ro[p*2] = make_float2(r0v, r1v);
        }
    }
}

// ---------------- K3: U = (X - mu_k) W_k, score = 2d + uRu - ||mu||^2 ----------
// grid (16, 256): 64-row b-tile x one k. 256 thr, 4x4 micro-tiles, e-packed f32x2.
__global__ __launch_bounds__(256) void k3_score(const float* __restrict__ X,
                                                const float* __restrict__ mu,
                                                const float* __restrict__ w)
{
    const int k  = blockIdx.y;
    const int b0 = blockIdx.x * 64;
    const int t  = threadIdx.x;
    const int tx = t & 15;   // e-group (e = tx*4..tx*4+3)
    const int ty = t >> 4;   // b-group (b = ty*4..ty*4+3)

    __shared__ float sAB[32*68 + 32*64];  // XsT[32][68] | Ws[32][64]; reused as Rs[64][64]
    __shared__ float UsT[64*68];          // [f][b], padded
    __shared__ float mus[32];
    __shared__ float qpart[64];

    float* XsT = sAB;            // stride 68
    float* Ws  = sAB + 32*68;    // stride 64
    float* Rs  = sAB;            // 4096 <= 4224 floats

    unsigned long long u2[4][2];
#pragma unroll
    for (int i = 0; i < 4; i++) { u2[i][0] = 0ULL; u2[i][1] = 0ULL; }
    float dacc = 0.f;

    for (int gc = 0; gc < G_; gc += 32) {
        for (int idx = t; idx < 2048; idx += 256) {
            int i = idx >> 5, j = idx & 31;
            XsT[j*68 + i] = X[(size_t)(b0 + i) * G_ + gc + j];
        }
        {
            const float* wsrc = w + ((size_t)k * G_ + gc) * E_;   // contiguous 2048
            for (int idx = t; idx < 2048; idx += 256) Ws[idx] = wsrc[idx];
        }
        if (t < 32) mus[t] = mu[(size_t)(gc + t) * K_ + k];
        __syncthreads();
#pragma unroll
        for (int j = 0; j < 32; j++) {
            float4 a = *(const float4*)&XsT[j*68 + ty*4];
            ulonglong2 wv = *(const ulonglong2*)&Ws[j*64 + tx*4];
            unsigned long long a0 = pk2(a.x, a.x);
            unsigned long long a1 = pk2(a.y, a.y);
            unsigned long long a2b = pk2(a.z, a.z);
            unsigned long long a3 = pk2(a.w, a.w);
            ffma2(u2[0][0], a0, wv.x);  ffma2(u2[0][1], a0, wv.y);
            ffma2(u2[1][0], a1, wv.x);  ffma2(u2[1][1], a1, wv.y);
            ffma2(u2[2][0], a2b, wv.x); ffma2(u2[2][1], a2b, wv.y);
            ffma2(u2[3][0], a3, wv.x);  ffma2(u2[3][1], a3, wv.y);
        }
        if (t < 64) {   // d_b = x_b . mu_k partial
            float dd = 0.f;
#pragma unroll
            for (int j = 0; j < 32; j++) dd += XsT[j*68 + t] * mus[j];
            dacc += dd;
        }
        __syncthreads();
    }

    // u = Xw - v  (unpack to scalars)
    float uacc[4][4];
    {
        const float4 v4 = *(const float4*)&gV[k*E_ + tx*4];
#pragma unroll
        for (int i = 0; i < 4; i++) {
            float2 lo = upk(u2[i][0]), hi = upk(u2[i][1]);
            uacc[i][0] = lo.x - v4.x; uacc[i][1] = lo.y - v4.y;
            uacc[i][2] = hi.x - v4.z; uacc[i][3] = hi.y - v4.w;
        }
    }
    // stage u transposed for the quadform GEMM; load R over the (now-dead) GEMM tiles
#pragma unroll
    for (int i = 0; i < 4; i++)
#pragma unroll
        for (int l = 0; l < 4; l++)
            UsT[(tx*4 + l)*68 + ty*4 + i] = uacc[i][l];
    {
        const float* Rk = gR + (size_t)k * 4096;
        for (int idx = t; idx < 4096; idx += 256) Rs[idx] = Rk[idx];
    }
    __syncthreads();

    // T = U * R  (packed accumulators), then s_b = sum_e T[b][e]*u[b][e]
    unsigned long long t2[4][2];
#pragma unroll
    for (int i = 0; i < 4; i++) { t2[i][0] = 0ULL; t2[i][1] = 0ULL; }
#pragma unroll
    for (int f = 0; f < 64; f++) {
        float4 uu = *(const float4*)&UsT[f*68 + ty*4];
        ulonglong2 rr = *(const ulonglong2*)&Rs[f*64 + tx*4];
        unsigned long long b0p = pk2(uu.x, uu.x);
        unsigned long long b1p = pk2(uu.y, uu.y);
        unsigned long long b2p = pk2(uu.z, uu.z);
        unsigned long long b3p = pk2(uu.w, uu.w);
        ffma2(t2[0][0], b0p, rr.x); ffma2(t2[0][1], b0p, rr.y);
        ffma2(t2[1][0], b1p, rr.x); ffma2(t2[1][1], b1p, rr.y);
        ffma2(t2[2][0], b2p, rr.x); ffma2(t2[2][1], b2p, rr.y);
        ffma2(t2[3][0], b3p, rr.x); ffma2(t2[3][1], b3p, rr.y);
    }
    float p[4];
#pragma unroll
    for (int i = 0; i < 4; i++) {
        float2 lo = upk(t2[i][0]), hi = upk(t2[i][1]);
        p[i] = lo.x*uacc[i][0] + lo.y*uacc[i][1] + hi.x*uacc[i][2] + hi.y*uacc[i][3];
#pragma unroll
        for (int ofs = 8; ofs > 0; ofs >>= 1)
            p[i] += __shfl_down_sync(0xffffffffu, p[i], ofs, 16);
    }
    if (tx == 0) {
#pragma unroll
        for (int i = 0; i < 4; i++) qpart[ty*4 + i] = p[i];
    }
    __syncthreads();
    if (t < 64) {
        // maximize  -||dx||^2  <=>  maximize  2*d + uRu - ||mu_k||^2
        gScore[(size_t)(b0 + t) * K_ + k] = 2.f*dacc + qpart[t] - gMunorm[k];
    }
}

// ---------------- K4: argmax over k (first-max tie-break, like jnp.argmax) -----
__global__ __launch_bounds__(256) void k4_argmax()
{
    int b = blockIdx.x;
    int t = threadIdx.x;
    __shared__ float sv[256];
    __shared__ int   si[256];
    sv[t] = gScore[(size_t)b * K_ + t];
    si[t] = t;
    __syncthreads();
    for (int s = 128; s > 0; s >>= 1) {
        if (t < s) {
            float v2 = sv[t + s]; int i2 = si[t + s];
            if (v2 > sv[t] || (v2 == sv[t] && i2 < si[t])) { sv[t] = v2; si[t] = i2; }
        }
        __syncthreads();
    }
    if (t == 0) gKmax[b] = si[0];
}

// ---------------- K5: decode winner: y = beta*u*S6*W^T + mu_k ------------------
__global__ __launch_bounds__(256) void k5_decode(const float* __restrict__ X,
                                                 const float* __restrict__ mu,
                                                 const float* __restrict__ w,
                                                 float* __restrict__ y)
{
    int b = blockIdx.x;
    int t = threadIdx.x;
    __shared__ float upart[4][64];
    __shared__ float us[64];
    __shared__ float z6[64];
    int k = gKmax[b];
    const float* wk = w + (size_t)k * G_ * E_;

    {   // u[e] = sum_g X[b][g]*wk[g][e] - v[k][e], 4-way g split
        int e = t & 63, gq = t >> 6;
        float a = 0.f;
        const float* xb = X + (size_t)b * G_;
#pragma unroll 16
        for (int g = gq*64; g < gq*64 + 64; g++) a += xb[g] * wk[(size_t)g*E_ + e];
        upart[gq][e] = a;
    }
    __syncthreads();
    if (t < 64) us[t] = upart[0][t] + upart[1][t] + upart[2][t] + upart[3][t] - gV[k*E_ + t];
    __syncthreads();
    if (t < 64) {
        const float* S6k = gS6 + (size_t)k * 4096;
        float a = 0.f;
#pragma unroll 16
        for (int f = 0; f < 64; f++) a += us[f] * S6k[f*64 + t];
        z6[t] = BETA_F * a;
    }
    __syncthreads();
    {
        int g = t;
        float a = 0.f;
        const float* wg = wk + (size_t)g * E_;
#pragma unroll
        for (int e = 0; e < 64; e++) a += z6[e] * wg[e];
        y[(size_t)b * G_ + g] = a + mu[(size_t)g * K_ + k];
    }
}

// ---------------- launch --------------------------------------------------------
extern "C" void kernel_launch(void* const* d_in, const int* in_sizes, int n_in,
                              void* d_out, int out_size)
{
    const float* X  = (const float*)d_in[0];   // images (B,G)
    const float* mu = (const float*)d_in[1];   // (G,K)
    const float* w  = (const float*)d_in[2];   // (K,G,E)
    float* y = (float*)d_out;                  // (B,G)

    k1_prep<<<K_, 256>>>(mu, w);
    k2_poly<<<K_, 256>>>();
    dim3 g3(B_/64, K_);
    k3_score<<<g3, 256>>>(X, mu, w);
    k4_argmax<<<B_, 256>>>();
    k5_decode<<<B_, 256>>>(X, mu, w, y);
}

// round 8
// speedup vs baseline: 1.1496x; 1.1496x over previous
#include <cuda_runtime.h>
#include <cstdint>
#include <cstddef>

#define B_ 1024
#define G_ 256
#define K_ 256
#define E_ 64
#define BETA_F 0.05f

// ---------------- scratch (__device__ globals: no runtime allocation) ----------
__device__ float gM [K_*E_*E_];   // 4 MB : M_k = W_k^T W_k
__device__ float gS6[K_*E_*E_];   // 4 MB : sum_{j=0..5} A^j
__device__ float gR [K_*E_*E_];   // 4 MB : 2b*S5 - b^2*S5*M*S5
__device__ float gV [K_*E_];      // 64KB : v_k = mu_k W_k
__device__ float gMunorm[K_];
__device__ float gScore[B_*K_];   // 1 MB
__device__ int   gKmax[B_];

// ---------------- K1: per-k  M, v, ||mu_k||^2 ----------------------------------
__global__ __launch_bounds__(256) void k1_prep(const float* __restrict__ mu,
                                               const float* __restrict__ w)
{
    int k = blockIdx.x;
    int t = threadIdx.x;
    __shared__ float Ws[64*64];   // [g][e] chunk of W_k
    __shared__ float mus[64];
    __shared__ float red[64];
    float acc[16];
#pragma unroll
    for (int i = 0; i < 16; i++) acc[i] = 0.f;
    float vacc = 0.f, mn = 0.f;
    const float* wk = w + (size_t)k * G_ * E_;
    for (int gc = 0; gc < G_; gc += 64) {
        const float* src = wk + (size_t)gc * E_;   // contiguous 4096 floats
        for (int idx = t; idx < 4096; idx += 256) Ws[idx] = src[idx];
        if (t < 64) mus[t] = mu[(size_t)(gc + t) * K_ + k];
        __syncthreads();
#pragma unroll
        for (int r = 0; r < 16; r++) {
            int idx = t + (r << 8);
            int e = idx >> 6, f = idx & 63;
            float a = 0.f;
#pragma unroll 16
            for (int g = 0; g < 64; g++) a += Ws[g*64 + e] * Ws[g*64 + f];
            acc[r] += a;
        }
        if (t < 64) {
            float va = 0.f;
#pragma unroll 16
            for (int g = 0; g < 64; g++) va += mus[g] * Ws[g*64 + t];
            vacc += va;
            mn += mus[t] * mus[t];
        }
        __syncthreads();
    }
    float* Mk = gM + (size_t)k * 4096;
#pragma unroll
    for (int r = 0; r < 16; r++) Mk[t + (r << 8)] = acc[r];
    if (t < 64) { gV[k*E_ + t] = vacc; red[t] = mn; }
    __syncthreads();
    if (t == 0) { float s = 0.f; for (int i = 0; i < 64; i++) s += red[i]; gMunorm[k] = s; }
}

// ---------------- K2: per-k  S6 and R ------------------------------------------
// S_{t+1} = I + A*S_t, A = (1-b)I - b*M.  S_1 = I; after 4 iters Ss = S5.
// S6 = I + (1-b)S5 - b*(M*S5).  R = 2b*S5 - b^2*(M*S5)*S5   (M,S commute, all sym.)
__global__ __launch_bounds__(256) void k2_poly()
{
    int k = blockIdx.x;
    int t = threadIdx.x;
    __shared__ float Ms[64*64];
    __shared__ float Ss[64*64];
    const float* Mk = gM + (size_t)k * 4096;
    for (int idx = t; idx < 4096; idx += 256) {
        Ms[idx] = Mk[idx];
        Ss[idx] = ((idx >> 6) == (idx & 63)) ? 1.f : 0.f;
    }
    __syncthreads();
    for (int it = 0; it < 4; it++) {
        float val[16];
#pragma unroll
        for (int r = 0; r < 16; r++) {
            int idx = t + (r << 8);
            int e = idx >> 6, f = idx & 63;
            float a = 0.f;
#pragma unroll 16
            for (int g = 0; g < 64; g++) a += Ms[e*64 + g] * Ss[g*64 + f];
            float v = (1.f - BETA_F) * Ss[idx] - BETA_F * a;
            if (e == f) v += 1.f;
            val[r] = v;
        }
        __syncthreads();
#pragma unroll
        for (int r = 0; r < 16; r++) Ss[t + (r << 8)] = val[r];
        __syncthreads();
    }
    // Ss = S5. Compute MS5 (into regs), S6 -> gmem, then overwrite Ms with MS5.
    float ms5[16];
#pragma unroll
    for (int r = 0; r < 16; r++) {
        int idx = t + (r << 8);
        int e = idx >> 6, f = idx & 63;
        float a = 0.f;
#pragma unroll 16
        for (int g = 0; g < 64; g++) a += Ms[e*64 + g] * Ss[g*64 + f];
        ms5[r] = a;
        float s6 = (1.f - BETA_F) * Ss[idx] - BETA_F * a;
        if (e == f) s6 += 1.f;
        gS6[(size_t)k*4096 + idx] = s6;
    }
    __syncthreads();
#pragma unroll
    for (int r = 0; r < 16; r++) Ms[t + (r << 8)] = ms5[r];
    __syncthreads();
#pragma unroll
    for (int r = 0; r < 16; r++) {
        int idx = t + (r << 8);
        int e = idx >> 6, f = idx & 63;
        float q = 0.f;
#pragma unroll 16
        for (int g = 0; g < 64; g++) q += Ms[e*64 + g] * Ss[g*64 + f];
        gR[(size_t)k*4096 + idx] = 2.f*BETA_F*Ss[idx] - BETA_F*BETA_F*q;
    }
}

// ---------------- K3: U = (X - mu_k) W_k, score = 2d + uRu - ||mu||^2 ----------
// grid (16, 256): 64-row b-tile x one k. 128 thr, 8x4 micro-tiles:
// per inner step 3x LDS.128 feed 32 FFMA (was 2:16) -> smem crossbar no longer
// co-saturated with the FMA pipe.
__global__ __launch_bounds__(128) void k3_score(const float* __restrict__ X,
                                                const float* __restrict__ mu,
                                                const float* __restrict__ w)
{
    const int k  = blockIdx.y;
    const int b0 = blockIdx.x * 64;
    const int t  = threadIdx.x;
    const int tx = t & 15;   // e-group (e = tx*4..tx*4+3)
    const int ty = t >> 4;   // b-group (b = ty*8..ty*8+7)

    __shared__ float sAB[32*68 + 32*64];  // XsT[32][68] | Ws[32][64]; reused as Rs[64][64]
    __shared__ float UsT[64*68];          // [f][b], padded
    __shared__ float mus[32];
    __shared__ float qpart[64];

    float* XsT = sAB;            // stride 68
    float* Ws  = sAB + 32*68;    // stride 64
    float* Rs  = sAB;            // 4096 <= 4224 floats

    float uacc[8][4];
#pragma unroll
    for (int i = 0; i < 8; i++)
#pragma unroll
        for (int l = 0; l < 4; l++) uacc[i][l] = 0.f;
    float dacc = 0.f;

    for (int gc = 0; gc < G_; gc += 32) {
        for (int idx = t; idx < 2048; idx += 128) {
            int i = idx >> 5, j = idx & 31;
            XsT[j*68 + i] = X[(size_t)(b0 + i) * G_ + gc + j];
        }
        {
            const float* wsrc = w + ((size_t)k * G_ + gc) * E_;   // contiguous 2048
            for (int idx = t; idx < 2048; idx += 128) Ws[idx] = wsrc[idx];
        }
        if (t < 32) mus[t] = mu[(size_t)(gc + t) * K_ + k];
        __syncthreads();
#pragma unroll
        for (int j = 0; j < 32; j++) {
            float4 a0 = *(const float4*)&XsT[j*68 + ty*8];
            float4 a1 = *(const float4*)&XsT[j*68 + ty*8 + 4];
            float4 wv = *(const float4*)&Ws [j*64 + tx*4];
            uacc[0][0] += a0.x*wv.x; uacc[0][1] += a0.x*wv.y; uacc[0][2] += a0.x*wv.z; uacc[0][3] += a0.x*wv.w;
            uacc[1][0] += a0.y*wv.x; uacc[1][1] += a0.y*wv.y; uacc[1][2] += a0.y*wv.z; uacc[1][3] += a0.y*wv.w;
            uacc[2][0] += a0.z*wv.x; uacc[2][1] += a0.z*wv.y; uacc[2][2] += a0.z*wv.z; uacc[2][3] += a0.z*wv.w;
            uacc[3][0] += a0.w*wv.x; uacc[3][1] += a0.w*wv.y; uacc[3][2] += a0.w*wv.z; uacc[3][3] += a0.w*wv.w;
            uacc[4][0] += a1.x*wv.x; uacc[4][1] += a1.x*wv.y; uacc[4][2] += a1.x*wv.z; uacc[4][3] += a1.x*wv.w;
            uacc[5][0] += a1.y*wv.x; uacc[5][1] += a1.y*wv.y; uacc[5][2] += a1.y*wv.z; uacc[5][3] += a1.y*wv.w;
            uacc[6][0] += a1.z*wv.x; uacc[6][1] += a1.z*wv.y; uacc[6][2] += a1.z*wv.z; uacc[6][3] += a1.z*wv.w;
            uacc[7][0] += a1.w*wv.x; uacc[7][1] += a1.w*wv.y; uacc[7][2] += a1.w*wv.z; uacc[7][3] += a1.w*wv.w;
        }
        if (t < 64) {   // d_b = x_b . mu_k partial
            float dd = 0.f;
#pragma unroll
            for (int j = 0; j < 32; j++) dd += XsT[j*68 + t] * mus[j];
            dacc += dd;
        }
        __syncthreads();
    }

    // u = Xw - v
    {
        const float4 v4 = *(const float4*)&gV[k*E_ + tx*4];
#pragma unroll
        for (int i = 0; i < 8; i++) {
            uacc[i][0] -= v4.x; uacc[i][1] -= v4.y; uacc[i][2] -= v4.z; uacc[i][3] -= v4.w;
        }
    }
    // stage u transposed for the quadform GEMM; load R over the (now-dead) GEMM tiles
#pragma unroll
    for (int i = 0; i < 8; i++)
#pragma unroll
        for (int l = 0; l < 4; l++)
            UsT[(tx*4 + l)*68 + ty*8 + i] = uacc[i][l];
    {
        const float* Rk = gR + (size_t)k * 4096;
        for (int idx = t; idx < 4096; idx += 128) Rs[idx] = Rk[idx];
    }
    __syncthreads();

    // T = U * R  (register accumulators), then s_b = sum_e T[b][e]*u[b][e]
    float tacc[8][4];
#pragma unroll
    for (int i = 0; i < 8; i++)
#pragma unroll
        for (int l = 0; l < 4; l++) tacc[i][l] = 0.f;
#pragma unroll
    for (int f = 0; f < 64; f++) {
        float4 u0 = *(const float4*)&UsT[f*68 + ty*8];
        float4 u1 = *(const float4*)&UsT[f*68 + ty*8 + 4];
        float4 rr = *(const float4*)&Rs [f*64 + tx*4];
        tacc[0][0] += u0.x*rr.x; tacc[0][1] += u0.x*rr.y; tacc[0][2] += u0.x*rr.z; tacc[0][3] += u0.x*rr.w;
        tacc[1][0] += u0.y*rr.x; tacc[1][1] += u0.y*rr.y; tacc[1][2] += u0.y*rr.z; tacc[1][3] += u0.y*rr.w;
        tacc[2][0] += u0.z*rr.x; tacc[2][1] += u0.z*rr.y; tacc[2][2] += u0.z*rr.z; tacc[2][3] += u0.z*rr.w;
        tacc[3][0] += u0.w*rr.x; tacc[3][1] += u0.w*rr.y; tacc[3][2] += u0.w*rr.z; tacc[3][3] += u0.w*rr.w;
        tacc[4][0] += u1.x*rr.x; tacc[4][1] += u1.x*rr.y; tacc[4][2] += u1.x*rr.z; tacc[4][3] += u1.x*rr.w;
        tacc[5][0] += u1.y*rr.x; tacc[5][1] += u1.y*rr.y; tacc[5][2] += u1.y*rr.z; tacc[5][3] += u1.y*rr.w;
        tacc[6][0] += u1.z*rr.x; tacc[6][1] += u1.z*rr.y; tacc[6][2] += u1.z*rr.z; tacc[6][3] += u1.z*rr.w;
        tacc[7][0] += u1.w*rr.x; tacc[7][1] += u1.w*rr.y; tacc[7][2] += u1.w*rr.z; tacc[7][3] += u1.w*rr.w;
    }
    float p[8];
#pragma unroll
    for (int i = 0; i < 8; i++) {
        p[i] = tacc[i][0]*uacc[i][0] + tacc[i][1]*uacc[i][1]
             + tacc[i][2]*uacc[i][2] + tacc[i][3]*uacc[i][3];
#pragma unroll
        for (int ofs = 8; ofs > 0; ofs >>= 1)
            p[i] += __shfl_down_sync(0xffffffffu, p[i], ofs, 16);
    }
    if (tx == 0) {
#pragma unroll
        for (int i = 0; i < 8; i++) qpart[ty*8 + i] = p[i];
    }
    __syncthreads();
    if (t < 64) {
        // maximize  -||dx||^2  <=>  maximize  2*d + uRu - ||mu_k||^2
        gScore[(size_t)(b0 + t) * K_ + k] = 2.f*dacc + qpart[t] - gMunorm[k];
    }
}

// ---------------- K4: argmax over k (first-max tie-break, like jnp.argmax) -----
__global__ __launch_bounds__(256) void k4_argmax()
{
    int b = blockIdx.x;
    int t = threadIdx.x;
    __shared__ float sv[256];
    __shared__ int   si[256];
    sv[t] = gScore[(size_t)b * K_ + t];
    si[t] = t;
    __syncthreads();
    for (int s = 128; s > 0; s >>= 1) {
        if (t < s) {
            float v2 = sv[t + s]; int i2 = si[t + s];
            if (v2 > sv[t] || (v2 == sv[t] && i2 < si[t])) { sv[t] = v2; si[t] = i2; }
        }
        __syncthreads();
    }
    if (t == 0) gKmax[b] = si[0];
}

// ---------------- K5: decode winner: y = beta*u*S6*W^T + mu_k ------------------
__global__ __launch_bounds__(256) void k5_decode(const float* __restrict__ X,
                                                 const float* __restrict__ mu,
                                                 const float* __restrict__ w,
                                                 float* __restrict__ y)
{
    int b = blockIdx.x;
    int t = threadIdx.x;
    __shared__ float upart[4][64];
    __shared__ float us[64];
    __shared__ float z6[64];
    int k = gKmax[b];
    const float* wk = w + (size_t)k * G_ * E_;

    {   // u[e] = sum_g X[b][g]*wk[g][e] - v[k][e], 4-way g split
        int e = t & 63, gq = t >> 6;
        float a = 0.f;
        const float* xb = X + (size_t)b * G_;
#pragma unroll 16
        for (int g = gq*64; g < gq*64 + 64; g++) a += xb[g] * wk[(size_t)g*E_ + e];
        upart[gq][e] = a;
    }
    __syncthreads();
    if (t < 64) us[t] = upart[0][t] + upart[1][t] + upart[2][t] + upart[3][t] - gV[k*E_ + t];
    __syncthreads();
    if (t < 64) {
        const float* S6k = gS6 + (size_t)k * 4096;
        float a = 0.f;
#pragma unroll 16
        for (int f = 0; f < 64; f++) a += us[f] * S6k[f*64 + t];
        z6[t] = BETA_F * a;
    }
    __syncthreads();
    {
        int g = t;
        float a = 0.f;
        const float* wg = wk + (size_t)g * E_;
#pragma unroll
        for (int e = 0; e < 64; e++) a += z6[e] * wg[e];
        y[(size_t)b * G_ + g] = a + mu[(size_t)g * K_ + k];
    }
}

// ---------------- launch --------------------------------------------------------
extern "C" void kernel_launch(void* const* d_in, const int* in_sizes, int n_in,
                              void* d_out, int out_size)
{
    const float* X  = (const float*)d_in[0];   // images (B,G)
    const float* mu = (const float*)d_in[1];   // (G,K)
    const float* w  = (const float*)d_in[2];   // (K,G,E)
    float* y = (float*)d_out;                  // (B,G)

    k1_prep<<<K_, 256>>>(mu, w);
    k2_poly<<<K_, 256>>>();
    dim3 g3(B_/64, K_);
    k3_score<<<g3, 128>>>(X, mu, w);
    k4_argmax<<<B_, 256>>>();
    k5_decode<<<B_, 256>>>(X, mu, w, y);
}